// round 1
// baseline (speedup 1.0000x reference)
#include <cuda_runtime.h>

// Problem: x (2,128,512,512) f32.
//   edge = sum_o |conv(sum_c x, sobel_o)|  (channel-independent)
//   out  = maxpool2x2(edge) broadcast to (2,128,256,256)
//
// K1: channel sum  (reads 256MB)          -> g_sum  (2,512,512)
// K2: sobel x4 + |.| + sum + maxpool 2x2  -> g_edge (2,256,256)
// K3: broadcast g_edge over 128 channels  (writes 64MB)

#define S_SPATIAL   (512 * 512)       // 262144
#define S_SPATIAL4  (S_SPATIAL / 4)   // 65536
#define E_SPATIAL   (256 * 256)       // 65536
#define NCH         128
#define NB          2

__device__ float g_sum[NB * S_SPATIAL];     // 2 MB scratch
__device__ float g_edge[NB * E_SPATIAL];    // 512 KB scratch

// ---------------- K1: channel sum (float4) ----------------
__global__ void __launch_bounds__(256) k_chansum(const float4* __restrict__ x) {
    int idx = blockIdx.x * blockDim.x + threadIdx.x;   // 0 .. 131071
    if (idx >= NB * S_SPATIAL4) return;
    int b  = idx >> 16;          // / 65536
    int sp = idx & 0xFFFF;
    const float4* p = x + (size_t)b * NCH * S_SPATIAL4 + sp;
    float4 acc = make_float4(0.f, 0.f, 0.f, 0.f);
#pragma unroll 8
    for (int c = 0; c < NCH; c++) {
        float4 v = p[(size_t)c * S_SPATIAL4];
        acc.x += v.x; acc.y += v.y; acc.z += v.z; acc.w += v.w;
    }
    ((float4*)g_sum)[idx] = acc;
}

// ---------------- K2: sobel(4) + abs-sum + maxpool ----------------
__device__ __forceinline__ float edge_at(const float p[4][4], int dy, int dx) {
    float a = p[dy][dx],     bb = p[dy][dx+1],   c = p[dy][dx+2];
    float d = p[dy+1][dx],                        f = p[dy+1][dx+2];
    float g = p[dy+2][dx],   h = p[dy+2][dx+1],  i = p[dy+2][dx+2];
    // XLA conv = cross-correlation (no kernel flip)
    float e0 = -a + c - 2.f*d + 2.f*f - g + i;            // [[-1,0,1],[-2,0,2],[-1,0,1]]
    float e1 =  a + 2.f*bb + c - g - 2.f*h - i;           // [[1,2,1],[0,0,0],[-1,-2,-1]]
    float e2 =  2.f*a + bb + d - f - h - 2.f*i;           // [[2,1,0],[1,0,-1],[0,-1,-2]]
    float e3 = -bb - 2.f*c + d - f + 2.f*g + h;           // [[0,-1,-2],[1,0,-1],[2,1,0]]
    return fabsf(e0) + fabsf(e1) + fabsf(e2) + fabsf(e3);
}

__global__ void __launch_bounds__(256) k_edgepool() {
    int idx = blockIdx.x * blockDim.x + threadIdx.x;   // 0 .. 131071
    if (idx >= NB * E_SPATIAL) return;
    int px = idx & 255;
    int py = (idx >> 8) & 255;
    int b  = idx >> 16;
    const float* s = g_sum + b * S_SPATIAL;

    int y0 = 2 * py - 1, x0 = 2 * px - 1;
    float patch[4][4];
#pragma unroll
    for (int r = 0; r < 4; r++) {
        int y = y0 + r;
        bool yok = (y >= 0) & (y < 512);
#pragma unroll
        for (int cix = 0; cix < 4; cix++) {
            int xx = x0 + cix;
            bool ok = yok & (xx >= 0) & (xx < 512);
            patch[r][cix] = ok ? s[y * 512 + xx] : 0.f;
        }
    }
    float m = fmaxf(fmaxf(edge_at(patch, 0, 0), edge_at(patch, 0, 1)),
                    fmaxf(edge_at(patch, 1, 0), edge_at(patch, 1, 1)));
    g_edge[idx] = m;
}

// ---------------- K3: broadcast over channels (float4) ----------------
__global__ void __launch_bounds__(256) k_broadcast(float4* __restrict__ out) {
    int idx = blockIdx.x * blockDim.x + threadIdx.x;   // 0 .. 4194303
    if (idx >= NB * NCH * E_SPATIAL / 4) return;
    int px4 = idx & 63;            // 256/4
    int py  = (idx >> 6) & 255;
    int bc  = idx >> 14;
    int b   = bc >> 7;             // channel index unused (broadcast)
    out[idx] = ((const float4*)g_edge)[((b << 8) + py) * 64 + px4];
}

extern "C" void kernel_launch(void* const* d_in, const int* in_sizes, int n_in,
                              void* d_out, int out_size) {
    const float4* x = (const float4*)d_in[0];
    float4* out = (float4*)d_out;

    k_chansum<<<(NB * S_SPATIAL4 + 255) / 256, 256>>>(x);
    k_edgepool<<<(NB * E_SPATIAL + 255) / 256, 256>>>();
    k_broadcast<<<(NB * NCH * E_SPATIAL / 4 + 255) / 256, 256>>>(out);
}

// round 2
// speedup vs baseline: 1.0466x; 1.0466x over previous
#include <cuda_runtime.h>

// Problem: x (2,128,512,512) f32.
//   edge = sum_o |conv(sum_c x, sobel_o)|  (channel-independent)
//   out  = maxpool2x2(edge) broadcast to (2,128,256,256)
//
// K1: channel sum (reads 256MB, streaming) -> g_sum (2,512,512)
// K2: per pooled row: sobel x4 + abs-sum + maxpool -> smem,
//     then broadcast-write 128 channels (writes 64MB, streaming)

#define S_SPATIAL   (512 * 512)       // 262144
#define S_SPATIAL4  (S_SPATIAL / 4)   // 65536
#define NCH         128
#define NB          2

__device__ float g_sum[NB * S_SPATIAL];     // 2 MB scratch

// ---------------- K1: channel sum (float4, streaming loads) ----------------
__global__ void __launch_bounds__(256) k_chansum(const float4* __restrict__ x) {
    int idx = blockIdx.x * blockDim.x + threadIdx.x;   // 0 .. 131071
    if (idx >= NB * S_SPATIAL4) return;
    int b  = idx >> 16;
    int sp = idx & 0xFFFF;
    const float4* p = x + (size_t)b * NCH * S_SPATIAL4 + sp;
    float4 acc = make_float4(0.f, 0.f, 0.f, 0.f);
#pragma unroll 16
    for (int c = 0; c < NCH; c++) {
        float4 v = __ldcs(p + (size_t)c * S_SPATIAL4);   // read-once: evict-first
        acc.x += v.x; acc.y += v.y; acc.z += v.z; acc.w += v.w;
    }
    ((float4*)g_sum)[idx] = acc;
}

// ---------------- K2 fused: edge+pool row -> broadcast 128 channels ----------------
__device__ __forceinline__ float edge_at(const float p[4][4], int dy, int dx) {
    float a = p[dy][dx],     bb = p[dy][dx+1],   c = p[dy][dx+2];
    float d = p[dy+1][dx],                        f = p[dy+1][dx+2];
    float g = p[dy+2][dx],   h = p[dy+2][dx+1],  i = p[dy+2][dx+2];
    // XLA conv = cross-correlation (no kernel flip)
    float e0 = -a + c - 2.f*d + 2.f*f - g + i;
    float e1 =  a + 2.f*bb + c - g - 2.f*h - i;
    float e2 =  2.f*a + bb + d - f - h - 2.f*i;
    float e3 = -bb - 2.f*c + d - f + 2.f*g + h;
    return fabsf(e0) + fabsf(e1) + fabsf(e2) + fabsf(e3);
}

__global__ void __launch_bounds__(256) k_edgecast(float4* __restrict__ out) {
    // one block = one (b, pooled-row py). grid = 2*256 = 512 blocks.
    int py = blockIdx.x & 255;
    int b  = blockIdx.x >> 8;
    int tid = threadIdx.x;           // = px, 0..255

    __shared__ float row[256];       // edge row
    {
        const float* s = g_sum + b * S_SPATIAL;
        int y0 = 2 * py - 1, x0 = 2 * tid - 1;
        float patch[4][4];
#pragma unroll
        for (int r = 0; r < 4; r++) {
            int y = y0 + r;
            bool yok = (y >= 0) & (y < 512);
#pragma unroll
            for (int cx = 0; cx < 4; cx++) {
                int xx = x0 + cx;
                bool ok = yok & (xx >= 0) & (xx < 512);
                patch[r][cx] = ok ? __ldg(s + y * 512 + xx) : 0.f;
            }
        }
        row[tid] = fmaxf(fmaxf(edge_at(patch, 0, 0), edge_at(patch, 0, 1)),
                         fmaxf(edge_at(patch, 1, 0), edge_at(patch, 1, 1)));
    }
    __syncthreads();

    // Broadcast write: 128 channels x 64 float4 per row = 8192 float4 / block.
    // Each iter: 256 threads write 4 channels' worth (4 x 64 float4), coalesced.
    int px4   = tid & 63;            // float4 index within row
    int csub  = tid >> 6;            // 0..3
    float4 v = ((const float4*)row)[px4];
    // out index for (b, c, py, px4): ((b*128 + c)*256 + py)*64 + px4
    float4* o = out + ((size_t)(b * NCH + csub) * 256 + py) * 64 + px4;
#pragma unroll 8
    for (int i = 0; i < 32; i++) {
        __stcs(o, v);                // written-once: streaming store
        o += (size_t)4 * 256 * 64;   // advance 4 channels
    }
}

extern "C" void kernel_launch(void* const* d_in, const int* in_sizes, int n_in,
                              void* d_out, int out_size) {
    const float4* x = (const float4*)d_in[0];
    float4* out = (float4*)d_out;

    k_chansum<<<(NB * S_SPATIAL4 + 255) / 256, 256>>>(x);
    k_edgecast<<<NB * 256, 256>>>(out);
}